// round 5
// baseline (speedup 1.0000x reference)
#include <cuda_runtime.h>
#include <cstdint>
#include <cstddef>

// ---------------- scratch (static device memory; no allocs allowed) ----------
// bufA: holds X0 (67 rows) and layer-1 outputs (<=128 rows), M <= 524288
// bufB: holds layer-0 (<=64) and layer-2 (<=256 rows) outputs
static __device__ float g_bufA[(size_t)128 * 524288];   // 256 MB
static __device__ float g_bufB[(size_t)256 * 524288];   // 512 MB
static __device__ float g_meanb[24];
static __device__ int   g_idxb[8 * 1024 * 64];
static __device__ float g_sum[256];
static __device__ float g_sq[256];
static __device__ float g_affa[256];
static __device__ float g_affd[256];

// ---------------- mean over N of xyz ----------------------------------------
__global__ void mean_kernel(const float* __restrict__ xyz, float* __restrict__ meanb)
{
    int b = blockIdx.x, tid = threadIdx.x;
    float sx = 0.f, sy = 0.f, sz = 0.f;
    for (int i = tid; i < 8192; i += 256) {
        const float* q = xyz + ((size_t)b * 8192 + i) * 3;
        sx += q[0]; sy += q[1]; sz += q[2];
    }
    __shared__ float sh[768];
    sh[tid] = sx; sh[256 + tid] = sy; sh[512 + tid] = sz;
    __syncthreads();
    for (int off = 128; off; off >>= 1) {
        if (tid < off) {
            sh[tid]       += sh[tid + off];
            sh[256 + tid] += sh[256 + tid + off];
            sh[512 + tid] += sh[512 + tid + off];
        }
        __syncthreads();
    }
    if (tid == 0) {
        meanb[b * 3 + 0] = sh[0]   / 8192.f;
        meanb[b * 3 + 1] = sh[256] / 8192.f;
        meanb[b * 3 + 2] = sh[512] / 8192.f;
    }
}

// ---------------- farthest point sampling (1024 steps, 8193 pts) -------------
__global__ void __launch_bounds__(1024) fps_kernel(
    const float* __restrict__ xyz, const float* __restrict__ meanb,
    float* __restrict__ nxyz)
{
    const int b = blockIdx.x, tid = threadIdx.x;
    const int N1 = 8193;
    float px[9], py[9], pz[9], dist[9];
#pragma unroll
    for (int j = 0; j < 9; ++j) {
        int p = j * 1024 + tid;
        if (p < N1) {
            if (p == 0) {
                px[j] = meanb[b * 3]; py[j] = meanb[b * 3 + 1]; pz[j] = meanb[b * 3 + 2];
            } else {
                const float* q = xyz + ((size_t)b * 8192 + (p - 1)) * 3;
                px[j] = q[0]; py[j] = q[1]; pz[j] = q[2];
            }
        } else { px[j] = 0.f; py[j] = 0.f; pz[j] = 0.f; }
        dist[j] = 1e10f;
    }
    __shared__ float sc[3];
    __shared__ unsigned long long wred[32];
    __shared__ int sfar;
    int far = 0;
    for (int t = 0; t < 1024; ++t) {
        if ((far & 1023) == tid) {
            int j = far >> 10;
            sc[0] = px[j]; sc[1] = py[j]; sc[2] = pz[j];
            float* o = nxyz + ((size_t)b * 1024 + t) * 3;
            o[0] = px[j]; o[1] = py[j]; o[2] = pz[j];
        }
        __syncthreads();
        float cx = sc[0], cy = sc[1], cz = sc[2];
        unsigned long long best = 0;
#pragma unroll
        for (int j = 0; j < 9; ++j) {
            int p = j * 1024 + tid;
            if (p < N1) {
                float dx = px[j] - cx, dy = py[j] - cy, dz = pz[j] - cz;
                // no-FMA sum-of-squares to match XLA mul+add lowering
                float d = __fadd_rn(__fadd_rn(__fmul_rn(dx, dx), __fmul_rn(dy, dy)),
                                    __fmul_rn(dz, dz));
                float nd = fminf(dist[j], d);
                dist[j] = nd;
                unsigned long long pk =
                    ((unsigned long long)__float_as_uint(nd) << 32) |
                    (unsigned long long)(0xFFFFFFFFu - (unsigned)p);
                if (pk > best) best = pk;
            }
        }
        for (int off = 16; off; off >>= 1) {
            unsigned long long o2 = __shfl_down_sync(0xFFFFFFFFu, best, off);
            if (o2 > best) best = o2;
        }
        if ((tid & 31) == 0) wred[tid >> 5] = best;
        __syncthreads();
        if (tid < 32) {
            best = wred[tid];
            for (int off = 16; off; off >>= 1) {
                unsigned long long o2 = __shfl_down_sync(0xFFFFFFFFu, best, off);
                if (o2 > best) best = o2;
            }
            if (tid == 0)
                sfar = (int)(0xFFFFFFFFu - (unsigned)(best & 0xFFFFFFFFull));
        }
        __syncthreads();
        far = sfar;
    }
}

// ---------------- ball query (first K ascending in-ball indices) -------------
__global__ void ball_kernel(const float* __restrict__ xyz,
                            const float* __restrict__ nxyz,
                            int* __restrict__ idx, float r2, int K)
{
    int w = (blockIdx.x * blockDim.x + threadIdx.x) >> 5;
    int lane = threadIdx.x & 31;
    if (w >= 8192) return;
    int b = w >> 10;
    float cx = nxyz[(size_t)w * 3], cy = nxyz[(size_t)w * 3 + 1], cz = nxyz[(size_t)w * 3 + 2];
    const float* X = xyz + (size_t)b * 8192 * 3;
    int cnt = 0, first = 0;
    int* out = idx + (size_t)w * K;
    for (int base = 0; base < 8192; base += 32) {
        int p = base + lane;
        float dx = X[p * 3] - cx, dy = X[p * 3 + 1] - cy, dz = X[p * 3 + 2] - cz;
        float d2 = __fadd_rn(__fadd_rn(__fmul_rn(dx, dx), __fmul_rn(dy, dy)),
                             __fmul_rn(dz, dz));
        bool in = d2 < r2;
        unsigned mask = __ballot_sync(0xFFFFFFFFu, in);
        if (cnt == 0 && mask) first = base + __ffs(mask) - 1;
        if (in) {
            int pos = cnt + __popc(mask & ((1u << lane) - 1u));
            if (pos < K) out[pos] = p;
        }
        cnt += __popc(mask);
        if (cnt >= K) break;
    }
    if (cnt < K) {
        for (int pos = cnt + lane; pos < K; pos += 32) out[pos] = first; // first=0 if none
    }
}

// ---------------- gather: build X0 = concat(rel, feats) as (67, M) -----------
__global__ void gather_kernel(const float* __restrict__ xyz,
                              const float* __restrict__ feat,
                              const float* __restrict__ nxyz,
                              const int* __restrict__ idx,
                              float* __restrict__ X0, int K)
{
    size_t M = (size_t)8192 * K;
    size_t m = (size_t)blockIdx.x * 256 + threadIdx.x;
    if (m >= M) return;
    int k = (int)(m % K);
    int bs = (int)(m / K);
    int b = bs >> 10;
    int p = idx[(size_t)bs * K + k];
    const float* pt = xyz + ((size_t)b * 8192 + p) * 3;
    const float* ct = nxyz + (size_t)bs * 3;
    X0[0 * M + m] = pt[0] - ct[0];
    X0[1 * M + m] = pt[1] - ct[1];
    X0[2 * M + m] = pt[2] - ct[2];
    const float* fb = feat + (size_t)b * 64 * 8192 + p;
#pragma unroll 4
    for (int c = 0; c < 64; ++c)
        X0[(size_t)(3 + c) * M + m] = fb[(size_t)c * 8192];
}

// ---------------- GEMM Y = W*act(X) with per-channel sum/sumsq ---------------
// W: (O,I) row-major; X: (I,M); Y: (O,M). act(x) = relu(aa[i]*x+ad[i]) if aa.
#define BO 64
#define BM 128
#define BK 16
__global__ void __launch_bounds__(128) gemm_stats_kernel(
    int O, int I, int M,
    const float* __restrict__ W, const float* __restrict__ X,
    float* __restrict__ Y,
    const float* __restrict__ aa, const float* __restrict__ ad,
    float* __restrict__ gsum, float* __restrict__ gsq)
{
    __shared__ float Ws[BK][BO];
    __shared__ float Xs[BK][BM];
    int tid = threadIdx.x;
    int tx = tid & 15, ty = tid >> 4;
    int mbase = blockIdx.x * BM;
    int obase = blockIdx.y * BO;
    float acc[8][8];
#pragma unroll
    for (int r = 0; r < 8; ++r)
#pragma unroll
        for (int c = 0; c < 8; ++c) acc[r][c] = 0.f;

    for (int kk = 0; kk < I; kk += BK) {
#pragma unroll
        for (int l = 0; l < 8; ++l) {
            int e = l * 128 + tid;
            int k = e >> 6, o = e & 63;
            int gk = kk + k;
            Ws[k][o] = (gk < I) ? W[(size_t)(obase + o) * I + gk] : 0.f;
        }
#pragma unroll
        for (int l = 0; l < BK; ++l) {
            int gk = kk + l;
            float v = 0.f;
            if (gk < I) {
                v = X[(size_t)gk * M + mbase + tid];
                if (aa) v = fmaxf(v * aa[gk] + ad[gk], 0.f);
            }
            Xs[l][tid] = v;
        }
        __syncthreads();
#pragma unroll
        for (int k = 0; k < BK; ++k) {
            float wr[8], xr[8];
#pragma unroll
            for (int r = 0; r < 8; ++r) wr[r] = Ws[k][ty * 8 + r];
#pragma unroll
            for (int c = 0; c < 8; ++c) xr[c] = Xs[k][tx * 8 + c];
#pragma unroll
            for (int r = 0; r < 8; ++r)
#pragma unroll
                for (int c = 0; c < 8; ++c)
                    acc[r][c] += wr[r] * xr[c];
        }
        __syncthreads();
    }

    float s1[8], s2[8];
#pragma unroll
    for (int r = 0; r < 8; ++r) {
        int o = obase + ty * 8 + r;
        size_t row = (size_t)o * M + mbase + tx * 8;
        float4 v0 = make_float4(acc[r][0], acc[r][1], acc[r][2], acc[r][3]);
        float4 v1 = make_float4(acc[r][4], acc[r][5], acc[r][6], acc[r][7]);
        *(float4*)(Y + row)     = v0;
        *(float4*)(Y + row + 4) = v1;
        float a = 0.f, b = 0.f;
#pragma unroll
        for (int c = 0; c < 8; ++c) { a += acc[r][c]; b += acc[r][c] * acc[r][c]; }
        s1[r] = a; s2[r] = b;
    }
#pragma unroll
    for (int off = 8; off; off >>= 1) {
#pragma unroll
        for (int r = 0; r < 8; ++r) {
            s1[r] += __shfl_xor_sync(0xFFFFFFFFu, s1[r], off);
            s2[r] += __shfl_xor_sync(0xFFFFFFFFu, s2[r], off);
        }
    }
    if (tx == 0) {
#pragma unroll
        for (int r = 0; r < 8; ++r) {
            int o = obase + ty * 8 + r;
            atomicAdd(&gsum[o], s1[r]);
            atomicAdd(&gsq[o], s2[r]);
        }
    }
}

// ---------------- BN finalize: a = g/sqrt(var+eps), d = b - mean*a -----------
__global__ void finalize_kernel(float* __restrict__ sum, float* __restrict__ sq,
                                const float* __restrict__ g, const float* __restrict__ bb,
                                float* __restrict__ aa, float* __restrict__ ad,
                                int O, float invn)
{
    int c = threadIdx.x;
    if (c < O) {
        float m = sum[c] * invn;
        float v = sq[c] * invn - m * m;
        float a = g[c] / sqrtf(v + 1e-5f);
        aa[c] = a;
        ad[c] = bb[c] - m * a;
    }
    if (c < 256) { sum[c] = 0.f; sq[c] = 0.f; }  // reset for next layer / replay
}

__global__ void zero_stats_kernel(float* __restrict__ s, float* __restrict__ q)
{
    int t = threadIdx.x;
    if (t < 256) { s[t] = 0.f; q[t] = 0.f; }
}

// ---------------- max over nsample, fused last-layer affine+relu -------------
__global__ void maxk_kernel(const float* __restrict__ Y,
                            const float* __restrict__ aa, const float* __restrict__ ad,
                            float* __restrict__ out, int O, int K, int coff)
{
    int gid = blockIdx.x * blockDim.x + threadIdx.x;
    int total = 8 * O * 1024;
    if (gid >= total) return;
    int s = gid & 1023;
    int c = (gid >> 10) % O;
    int b = gid / (O * 1024);
    size_t M = (size_t)8192 * K;
    const float* p = Y + (size_t)c * M + (size_t)(b * 1024 + s) * K;
    float a = aa[c], d = ad[c];
    float mx = -1e30f;
    for (int k = 0; k < K; k += 4) {
        float4 v = *(const float4*)(p + k);
        mx = fmaxf(mx, fmaxf(v.x * a + d, 0.f));
        mx = fmaxf(mx, fmaxf(v.y * a + d, 0.f));
        mx = fmaxf(mx, fmaxf(v.z * a + d, 0.f));
        mx = fmaxf(mx, fmaxf(v.w * a + d, 0.f));
    }
    out[((size_t)b * 384 + coff + c) * 1024 + s] = mx;
}

// ---------------- host launch ------------------------------------------------
extern "C" void kernel_launch(void* const* d_in, const int* in_sizes, int n_in,
                              void* d_out, int out_size)
{
    (void)in_sizes; (void)n_in; (void)out_size;
    const float* xyz  = (const float*)d_in[0];
    const float* feat = (const float*)d_in[1];
    const float* W[2][3]; const float* G[2][3]; const float* Bb[2][3];
    for (int bi = 0; bi < 2; ++bi)
        for (int li = 0; li < 3; ++li) {
            W[bi][li]  = (const float*)d_in[2 + bi * 9 + li * 3 + 0];
            G[bi][li]  = (const float*)d_in[2 + bi * 9 + li * 3 + 1];
            Bb[bi][li] = (const float*)d_in[2 + bi * 9 + li * 3 + 2];
        }
    float* out      = (float*)d_out;
    float* nxyz     = out;            // (8,1024,3)
    float* feat_out = out + 24576;    // (8,384,1024)

    float *bufA, *bufB, *meanb, *sum, *sq, *aa, *ad; int* idxb;
    cudaGetSymbolAddress((void**)&bufA, g_bufA);
    cudaGetSymbolAddress((void**)&bufB, g_bufB);
    cudaGetSymbolAddress((void**)&meanb, g_meanb);
    cudaGetSymbolAddress((void**)&idxb, g_idxb);
    cudaGetSymbolAddress((void**)&sum, g_sum);
    cudaGetSymbolAddress((void**)&sq, g_sq);
    cudaGetSymbolAddress((void**)&aa, g_affa);
    cudaGetSymbolAddress((void**)&ad, g_affd);

    mean_kernel<<<8, 256>>>(xyz, meanb);
    fps_kernel<<<8, 1024>>>(xyz, meanb, nxyz);
    zero_stats_kernel<<<1, 256>>>(sum, sq);

    const int OS[2][4] = { {67, 64, 64, 128}, {67, 64, 128, 256} };
    const int KS[2] = {32, 64};
    const float R2[2] = { (float)(0.4 * 0.4), (float)(0.8 * 0.8) };

    for (int bi = 0; bi < 2; ++bi) {
        int K = KS[bi];
        int M = 8192 * K;
        float invn = 1.0f / (float)M;

        ball_kernel<<<2048, 128>>>(xyz, nxyz, idxb, R2[bi], K);
        gather_kernel<<<(M + 255) / 256, 256>>>(xyz, feat, nxyz, idxb, bufA, K);

        // L0: (O1 x 67) * X0 -> bufB
        {
            dim3 grid(M / BM, OS[bi][1] / BO);
            gemm_stats_kernel<<<grid, 128>>>(OS[bi][1], OS[bi][0], M, W[bi][0],
                                             bufA, bufB, nullptr, nullptr, sum, sq);
            finalize_kernel<<<1, 256>>>(sum, sq, G[bi][0], Bb[bi][0], aa, ad, OS[bi][1], invn);
        }
        // L1: (O2 x O1) * act(bufB) -> bufA
        {
            dim3 grid(M / BM, OS[bi][2] / BO);
            gemm_stats_kernel<<<grid, 128>>>(OS[bi][2], OS[bi][1], M, W[bi][1],
                                             bufB, bufA, aa, ad, sum, sq);
            finalize_kernel<<<1, 256>>>(sum, sq, G[bi][1], Bb[bi][1], aa, ad, OS[bi][2], invn);
        }
        // L2: (O3 x O2) * act(bufA) -> bufB
        {
            dim3 grid(M / BM, OS[bi][3] / BO);
            gemm_stats_kernel<<<grid, 128>>>(OS[bi][3], OS[bi][2], M, W[bi][2],
                                             bufA, bufB, aa, ad, sum, sq);
            finalize_kernel<<<1, 256>>>(sum, sq, G[bi][2], Bb[bi][2], aa, ad, OS[bi][3], invn);
        }
        // max over K with fused last affine+relu
        {
            int total = 8 * OS[bi][3] * 1024;
            maxk_kernel<<<(total + 255) / 256, 256>>>(bufB, aa, ad, feat_out,
                                                      OS[bi][3], K, bi == 0 ? 0 : 128);
        }
    }
}

// round 6
// speedup vs baseline: 1.4881x; 1.4881x over previous
#include <cuda_runtime.h>
#include <cstdint>
#include <cstddef>

// ---------------- scratch (static device memory; no allocs allowed) ----------
static __device__ float g_bufA[(size_t)128 * 524288];   // 256 MB
static __device__ float g_bufB[(size_t)256 * 524288];   // 512 MB
static __device__ float g_meanb[24];
static __device__ int   g_idxb[8 * 1024 * 64];
static __device__ float g_sum[256];
static __device__ float g_sq[256];
static __device__ float g_affa[256];
static __device__ float g_affd[256];

// ---------------- mean over N of xyz ----------------------------------------
__global__ void mean_kernel(const float* __restrict__ xyz, float* __restrict__ meanb)
{
    int b = blockIdx.x, tid = threadIdx.x;
    float sx = 0.f, sy = 0.f, sz = 0.f;
    for (int i = tid; i < 8192; i += 256) {
        const float* q = xyz + ((size_t)b * 8192 + i) * 3;
        sx += q[0]; sy += q[1]; sz += q[2];
    }
    __shared__ float sh[768];
    sh[tid] = sx; sh[256 + tid] = sy; sh[512 + tid] = sz;
    __syncthreads();
    for (int off = 128; off; off >>= 1) {
        if (tid < off) {
            sh[tid]       += sh[tid + off];
            sh[256 + tid] += sh[256 + tid + off];
            sh[512 + tid] += sh[512 + tid + off];
        }
        __syncthreads();
    }
    if (tid == 0) {
        meanb[b * 3 + 0] = sh[0]   / 8192.f;
        meanb[b * 3 + 1] = sh[256] / 8192.f;
        meanb[b * 3 + 2] = sh[512] / 8192.f;
    }
}

// ---------------- farthest point sampling (1024 steps, 8193 pts) -------------
__global__ void __launch_bounds__(1024) fps_kernel(
    const float* __restrict__ xyz, const float* __restrict__ meanb,
    float* __restrict__ nxyz)
{
    const int b = blockIdx.x, tid = threadIdx.x;
    const int N1 = 8193;
    float px[9], py[9], pz[9], dist[9];
#pragma unroll
    for (int j = 0; j < 9; ++j) {
        int p = j * 1024 + tid;
        if (p < N1) {
            if (p == 0) {
                px[j] = meanb[b * 3]; py[j] = meanb[b * 3 + 1]; pz[j] = meanb[b * 3 + 2];
            } else {
                const float* q = xyz + ((size_t)b * 8192 + (p - 1)) * 3;
                px[j] = q[0]; py[j] = q[1]; pz[j] = q[2];
            }
        } else { px[j] = 0.f; py[j] = 0.f; pz[j] = 0.f; }
        dist[j] = 1e10f;
    }
    __shared__ float sc[3];
    __shared__ unsigned long long wred[32];
    __shared__ int sfar;
    int far = 0;
    for (int t = 0; t < 1024; ++t) {
        if ((far & 1023) == tid) {
            int j = far >> 10;
            sc[0] = px[j]; sc[1] = py[j]; sc[2] = pz[j];
            float* o = nxyz + ((size_t)b * 1024 + t) * 3;
            o[0] = px[j]; o[1] = py[j]; o[2] = pz[j];
        }
        __syncthreads();
        float cx = sc[0], cy = sc[1], cz = sc[2];
        unsigned long long best = 0;
#pragma unroll
        for (int j = 0; j < 9; ++j) {
            int p = j * 1024 + tid;
            if (p < N1) {
                float dx = px[j] - cx, dy = py[j] - cy, dz = pz[j] - cz;
                float d = __fadd_rn(__fadd_rn(__fmul_rn(dx, dx), __fmul_rn(dy, dy)),
                                    __fmul_rn(dz, dz));
                float nd = fminf(dist[j], d);
                dist[j] = nd;
                unsigned long long pk =
                    ((unsigned long long)__float_as_uint(nd) << 32) |
                    (unsigned long long)(0xFFFFFFFFu - (unsigned)p);
                if (pk > best) best = pk;
            }
        }
        for (int off = 16; off; off >>= 1) {
            unsigned long long o2 = __shfl_down_sync(0xFFFFFFFFu, best, off);
            if (o2 > best) best = o2;
        }
        if ((tid & 31) == 0) wred[tid >> 5] = best;
        __syncthreads();
        if (tid < 32) {
            best = wred[tid];
            for (int off = 16; off; off >>= 1) {
                unsigned long long o2 = __shfl_down_sync(0xFFFFFFFFu, best, off);
                if (o2 > best) best = o2;
            }
            if (tid == 0)
                sfar = (int)(0xFFFFFFFFu - (unsigned)(best & 0xFFFFFFFFull));
        }
        __syncthreads();
        far = sfar;
    }
}

// ---------------- ball query (first K ascending in-ball indices) -------------
__global__ void ball_kernel(const float* __restrict__ xyz,
                            const float* __restrict__ nxyz,
                            int* __restrict__ idx, float r2, int K)
{
    int w = (blockIdx.x * blockDim.x + threadIdx.x) >> 5;
    int lane = threadIdx.x & 31;
    if (w >= 8192) return;
    int b = w >> 10;
    float cx = nxyz[(size_t)w * 3], cy = nxyz[(size_t)w * 3 + 1], cz = nxyz[(size_t)w * 3 + 2];
    const float* X = xyz + (size_t)b * 8192 * 3;
    int cnt = 0, first = 0;
    int* out = idx + (size_t)w * K;
    for (int base = 0; base < 8192; base += 32) {
        int p = base + lane;
        float dx = X[p * 3] - cx, dy = X[p * 3 + 1] - cy, dz = X[p * 3 + 2] - cz;
        float d2 = __fadd_rn(__fadd_rn(__fmul_rn(dx, dx), __fmul_rn(dy, dy)),
                             __fmul_rn(dz, dz));
        bool in = d2 < r2;
        unsigned mask = __ballot_sync(0xFFFFFFFFu, in);
        if (cnt == 0 && mask) first = base + __ffs(mask) - 1;
        if (in) {
            int pos = cnt + __popc(mask & ((1u << lane) - 1u));
            if (pos < K) out[pos] = p;
        }
        cnt += __popc(mask);
        if (cnt >= K) break;
    }
    if (cnt < K) {
        for (int pos = cnt + lane; pos < K; pos += 32) out[pos] = first;
    }
}

// ---------------- gather: build X0 = concat(rel, feats) as (67, M) -----------
__global__ void gather_kernel(const float* __restrict__ xyz,
                              const float* __restrict__ feat,
                              const float* __restrict__ nxyz,
                              const int* __restrict__ idx,
                              float* __restrict__ X0, int K)
{
    size_t M = (size_t)8192 * K;
    size_t m = (size_t)blockIdx.x * 256 + threadIdx.x;
    if (m >= M) return;
    int k = (int)(m % K);
    int bs = (int)(m / K);
    int b = bs >> 10;
    int p = idx[(size_t)bs * K + k];
    const float* pt = xyz + ((size_t)b * 8192 + p) * 3;
    const float* ct = nxyz + (size_t)bs * 3;
    X0[0 * M + m] = pt[0] - ct[0];
    X0[1 * M + m] = pt[1] - ct[1];
    X0[2 * M + m] = pt[2] - ct[2];
    const float* fb = feat + (size_t)b * 64 * 8192 + p;
#pragma unroll 4
    for (int c = 0; c < 64; ++c)
        X0[(size_t)(3 + c) * M + m] = fb[(size_t)c * 8192];
}

// ---------------- tf32 helpers ----------------------------------------------
__device__ __forceinline__ float to_tf32(float x)
{
    uint32_t r;
    asm volatile("cvt.rna.tf32.f32 %0, %1;\n" : "=r"(r) : "f"(x));
    return __uint_as_float(r);
}

__device__ __forceinline__ void mma_tf32(float* d, const uint32_t* a, const uint32_t* b)
{
    asm volatile(
        "mma.sync.aligned.m16n8k8.row.col.f32.tf32.tf32.f32 "
        "{%0,%1,%2,%3}, {%4,%5,%6,%7}, {%8,%9}, {%0,%1,%2,%3};\n"
        : "+f"(d[0]), "+f"(d[1]), "+f"(d[2]), "+f"(d[3])
        : "r"(a[0]), "r"(a[1]), "r"(a[2]), "r"(a[3]),
          "r"(b[0]), "r"(b[1]));
}

// ---------------- tensor-core GEMM: Y = W*act(X), with per-channel stats -----
// W: (O,I) row-major; X: (I,M); Y: (O,M). act(x) = relu(aa[i]*x+ad[i]) if aa.
// Block tile 64(O) x 256(M) x 32(K), 8 warps (2 x 4), warp tile 32x64.
#define TBO 64
#define TBM 256
#define TBK 32
#define WPAD 72
#define XPAD (TBM + 8)
__global__ void __launch_bounds__(256) gemm_tc_kernel(
    int O, int I, int M,
    const float* __restrict__ W, const float* __restrict__ X,
    float* __restrict__ Y,
    const float* __restrict__ aa, const float* __restrict__ ad,
    float* __restrict__ gsum, float* __restrict__ gsq)
{
    __shared__ float Wt[TBK][WPAD];
    __shared__ float Xt[TBK][XPAD];
    __shared__ float ssum[TBO], ssq[TBO];

    int tid = threadIdx.x, lane = tid & 31, wid = tid >> 5;
    int warpO = wid >> 2, warpM = wid & 3;      // 2 x 4 warp grid
    int ob = blockIdx.y * TBO, mb = blockIdx.x * TBM;

    if (tid < TBO) { ssum[tid] = 0.f; ssq[tid] = 0.f; }

    float acc[2][8][4];
#pragma unroll
    for (int r = 0; r < 2; ++r)
#pragma unroll
        for (int nt = 0; nt < 8; ++nt)
#pragma unroll
            for (int c = 0; c < 4; ++c) acc[r][nt][c] = 0.f;

    int r0 = lane >> 2, kq = lane & 3;

    for (int kk = 0; kk < I; kk += TBK) {
        // W tile: 64 o x 32 k -> Wt[k][o]
#pragma unroll
        for (int l = 0; l < 8; ++l) {
            int e = l * 256 + tid;
            int o = e >> 5, k = e & 31;
            int gk = kk + k;
            float v = (gk < I) ? W[(size_t)(ob + o) * I + gk] : 0.f;
            Wt[k][o] = to_tf32(v);
        }
        // X tile: 32 k x 256 m (float4 loads, fused affine+relu)
#pragma unroll
        for (int l = 0; l < 8; ++l) {
            int e = l * 256 + tid;
            int k = e >> 6, c4 = (e & 63) * 4;
            int gk = kk + k;
            float4 v = make_float4(0.f, 0.f, 0.f, 0.f);
            if (gk < I) {
                v = *(const float4*)(X + (size_t)gk * M + mb + c4);
                if (aa) {
                    float A_ = aa[gk], D_ = ad[gk];
                    v.x = fmaxf(v.x * A_ + D_, 0.f);
                    v.y = fmaxf(v.y * A_ + D_, 0.f);
                    v.z = fmaxf(v.z * A_ + D_, 0.f);
                    v.w = fmaxf(v.w * A_ + D_, 0.f);
                }
            }
            Xt[k][c4 + 0] = to_tf32(v.x);
            Xt[k][c4 + 1] = to_tf32(v.y);
            Xt[k][c4 + 2] = to_tf32(v.z);
            Xt[k][c4 + 3] = to_tf32(v.w);
        }
        __syncthreads();

#pragma unroll
        for (int k8 = 0; k8 < 4; ++k8) {
            int kb = k8 * 8;
            uint32_t afr[2][4], bfr[8][2];
#pragma unroll
            for (int r = 0; r < 2; ++r) {
                int o = warpO * 32 + r * 16 + r0;
                afr[r][0] = __float_as_uint(Wt[kb + kq][o]);
                afr[r][1] = __float_as_uint(Wt[kb + kq][o + 8]);
                afr[r][2] = __float_as_uint(Wt[kb + kq + 4][o]);
                afr[r][3] = __float_as_uint(Wt[kb + kq + 4][o + 8]);
            }
#pragma unroll
            for (int nt = 0; nt < 8; ++nt) {
                int m = warpM * 64 + nt * 8 + r0;
                bfr[nt][0] = __float_as_uint(Xt[kb + kq][m]);
                bfr[nt][1] = __float_as_uint(Xt[kb + kq + 4][m]);
            }
#pragma unroll
            for (int r = 0; r < 2; ++r)
#pragma unroll
                for (int nt = 0; nt < 8; ++nt)
                    mma_tf32(acc[r][nt], afr[r], bfr[nt]);
        }
        __syncthreads();
    }

    // epilogue: store Y, reduce per-channel sum/sumsq
#pragma unroll
    for (int r = 0; r < 2; ++r) {
#pragma unroll
        for (int half = 0; half < 2; ++half) {
            int o = warpO * 32 + r * 16 + r0 + half * 8;
            size_t rowoff = (size_t)(ob + o) * M + mb + warpM * 64 + kq * 2;
            float s = 0.f, q = 0.f;
#pragma unroll
            for (int nt = 0; nt < 8; ++nt) {
                float v0 = acc[r][nt][half * 2 + 0];
                float v1 = acc[r][nt][half * 2 + 1];
                *(float2*)(Y + rowoff + nt * 8) = make_float2(v0, v1);
                s += v0 + v1;
                q += v0 * v0 + v1 * v1;
            }
            s += __shfl_xor_sync(0xFFFFFFFFu, s, 1);
            q += __shfl_xor_sync(0xFFFFFFFFu, q, 1);
            s += __shfl_xor_sync(0xFFFFFFFFu, s, 2);
            q += __shfl_xor_sync(0xFFFFFFFFu, q, 2);
            if (kq == 0) {
                atomicAdd(&ssum[o], s);
                atomicAdd(&ssq[o], q);
            }
        }
    }
    __syncthreads();
    if (tid < TBO) {
        atomicAdd(&gsum[ob + tid], ssum[tid]);
        atomicAdd(&gsq[ob + tid], ssq[tid]);
    }
}

// ---------------- BN finalize: a = g/sqrt(var+eps), d = b - mean*a -----------
__global__ void finalize_kernel(float* __restrict__ sum, float* __restrict__ sq,
                                const float* __restrict__ g, const float* __restrict__ bb,
                                float* __restrict__ aa, float* __restrict__ ad,
                                int O, float invn)
{
    int c = threadIdx.x;
    if (c < O) {
        float m = sum[c] * invn;
        float v = sq[c] * invn - m * m;
        float a = g[c] / sqrtf(v + 1e-5f);
        aa[c] = a;
        ad[c] = bb[c] - m * a;
    }
    if (c < 256) { sum[c] = 0.f; sq[c] = 0.f; }
}

__global__ void zero_stats_kernel(float* __restrict__ s, float* __restrict__ q)
{
    int t = threadIdx.x;
    if (t < 256) { s[t] = 0.f; q[t] = 0.f; }
}

// ---------------- max over nsample, fused last-layer affine+relu -------------
__global__ void maxk_kernel(const float* __restrict__ Y,
                            const float* __restrict__ aa, const float* __restrict__ ad,
                            float* __restrict__ out, int O, int K, int coff)
{
    int gid = blockIdx.x * blockDim.x + threadIdx.x;
    int total = 8 * O * 1024;
    if (gid >= total) return;
    int s = gid & 1023;
    int c = (gid >> 10) % O;
    int b = gid / (O * 1024);
    size_t M = (size_t)8192 * K;
    const float* p = Y + (size_t)c * M + (size_t)(b * 1024 + s) * K;
    float a = aa[c], d = ad[c];
    float mx = -1e30f;
    for (int k = 0; k < K; k += 4) {
        float4 v = *(const float4*)(p + k);
        mx = fmaxf(mx, fmaxf(v.x * a + d, 0.f));
        mx = fmaxf(mx, fmaxf(v.y * a + d, 0.f));
        mx = fmaxf(mx, fmaxf(v.z * a + d, 0.f));
        mx = fmaxf(mx, fmaxf(v.w * a + d, 0.f));
    }
    out[((size_t)b * 384 + coff + c) * 1024 + s] = mx;
}

// ---------------- host launch ------------------------------------------------
extern "C" void kernel_launch(void* const* d_in, const int* in_sizes, int n_in,
                              void* d_out, int out_size)
{
    (void)in_sizes; (void)n_in; (void)out_size;
    const float* xyz  = (const float*)d_in[0];
    const float* feat = (const float*)d_in[1];
    const float* W[2][3]; const float* G[2][3]; const float* Bb[2][3];
    for (int bi = 0; bi < 2; ++bi)
        for (int li = 0; li < 3; ++li) {
            W[bi][li]  = (const float*)d_in[2 + bi * 9 + li * 3 + 0];
            G[bi][li]  = (const float*)d_in[2 + bi * 9 + li * 3 + 1];
            Bb[bi][li] = (const float*)d_in[2 + bi * 9 + li * 3 + 2];
        }
    float* out      = (float*)d_out;
    float* nxyz     = out;            // (8,1024,3)
    float* feat_out = out + 24576;    // (8,384,1024)

    float *bufA, *bufB, *meanb, *sum, *sq, *aa, *ad; int* idxb;
    cudaGetSymbolAddress((void**)&bufA, g_bufA);
    cudaGetSymbolAddress((void**)&bufB, g_bufB);
    cudaGetSymbolAddress((void**)&meanb, g_meanb);
    cudaGetSymbolAddress((void**)&idxb, g_idxb);
    cudaGetSymbolAddress((void**)&sum, g_sum);
    cudaGetSymbolAddress((void**)&sq, g_sq);
    cudaGetSymbolAddress((void**)&aa, g_affa);
    cudaGetSymbolAddress((void**)&ad, g_affd);

    mean_kernel<<<8, 256>>>(xyz, meanb);
    fps_kernel<<<8, 1024>>>(xyz, meanb, nxyz);
    zero_stats_kernel<<<1, 256>>>(sum, sq);

    const int OS[2][4] = { {67, 64, 64, 128}, {67, 64, 128, 256} };
    const int KS[2] = {32, 64};
    const float R2[2] = { (float)(0.4 * 0.4), (float)(0.8 * 0.8) };

    for (int bi = 0; bi < 2; ++bi) {
        int K = KS[bi];
        int M = 8192 * K;
        float invn = 1.0f / (float)M;

        ball_kernel<<<2048, 128>>>(xyz, nxyz, idxb, R2[bi], K);
        gather_kernel<<<(M + 255) / 256, 256>>>(xyz, feat, nxyz, idxb, bufA, K);

        // L0: (O1 x 67) * X0 -> bufB
        {
            dim3 grid(M / TBM, OS[bi][1] / TBO);
            gemm_tc_kernel<<<grid, 256>>>(OS[bi][1], OS[bi][0], M, W[bi][0],
                                          bufA, bufB, nullptr, nullptr, sum, sq);
            finalize_kernel<<<1, 256>>>(sum, sq, G[bi][0], Bb[bi][0], aa, ad, OS[bi][1], invn);
        }
        // L1: (O2 x O1) * act(bufB) -> bufA
        {
            dim3 grid(M / TBM, OS[bi][2] / TBO);
            gemm_tc_kernel<<<grid, 256>>>(OS[bi][2], OS[bi][1], M, W[bi][1],
                                          bufB, bufA, aa, ad, sum, sq);
            finalize_kernel<<<1, 256>>>(sum, sq, G[bi][1], Bb[bi][1], aa, ad, OS[bi][2], invn);
        }
        // L2: (O3 x O2) * act(bufA) -> bufB
        {
            dim3 grid(M / TBM, OS[bi][3] / TBO);
            gemm_tc_kernel<<<grid, 256>>>(OS[bi][3], OS[bi][2], M, W[bi][2],
                                          bufA, bufB, aa, ad, sum, sq);
            finalize_kernel<<<1, 256>>>(sum, sq, G[bi][2], Bb[bi][2], aa, ad, OS[bi][3], invn);
        }
        // max over K with fused last affine+relu
        {
            int total = 8 * OS[bi][3] * 1024;
            maxk_kernel<<<(total + 255) / 256, 256>>>(bufB, aa, ad, feat_out,
                                                      OS[bi][3], K, bi == 0 ? 0 : 128);
        }
    }
}

// round 7
// speedup vs baseline: 1.7198x; 1.1557x over previous
#include <cuda_runtime.h>
#include <cstdint>
#include <cstddef>

// ---------------- scratch (static device memory; no allocs allowed) ----------
static __device__ float g_bufA[(size_t)128 * 524288];   // 256 MB
static __device__ float g_bufB[(size_t)128 * 524288];   // 256 MB (L0/L1 outputs only now)
static __device__ float g_meanb[24];
static __device__ int   g_idxb[8 * 1024 * 64];
static __device__ float g_sum[256];
static __device__ float g_sq[256];
static __device__ float g_affa[256];
static __device__ float g_affd[256];
static __device__ float g_wt[65536];                    // pre-transposed tf32 weights
static __device__ unsigned g_emax[256 * 8192];          // 8 MB encoded max
static __device__ unsigned g_emin[256 * 8192];          // 8 MB encoded max of -y

// ---------------- helpers ----------------------------------------------------
__device__ __forceinline__ float to_tf32(float x)
{
    uint32_t r;
    asm volatile("cvt.rna.tf32.f32 %0, %1;\n" : "=r"(r) : "f"(x));
    return __uint_as_float(r);
}
__device__ __forceinline__ void mma_tf32(float* d, const uint32_t* a, const uint32_t* b)
{
    asm volatile(
        "mma.sync.aligned.m16n8k8.row.col.f32.tf32.tf32.f32 "
        "{%0,%1,%2,%3}, {%4,%5,%6,%7}, {%8,%9}, {%0,%1,%2,%3};\n"
        : "+f"(d[0]), "+f"(d[1]), "+f"(d[2]), "+f"(d[3])
        : "r"(a[0]), "r"(a[1]), "r"(a[2]), "r"(a[3]),
          "r"(b[0]), "r"(b[1]));
}
__device__ __forceinline__ void cp16(void* dst, const void* src)
{
    uint32_t d = (uint32_t)__cvta_generic_to_shared(dst);
    asm volatile("cp.async.ca.shared.global [%0], [%1], 16;\n" :: "r"(d), "l"(src));
}
__device__ __forceinline__ unsigned encf(float f)
{
    unsigned u = __float_as_uint(f);
    return (u >> 31) ? ~u : (u | 0x80000000u);
}
__device__ __forceinline__ float decf(unsigned u)
{
    return __uint_as_float((u >> 31) ? (u & 0x7FFFFFFFu) : ~u);
}

// ---------------- mean over N of xyz ----------------------------------------
__global__ void mean_kernel(const float* __restrict__ xyz, float* __restrict__ meanb)
{
    int b = blockIdx.x, tid = threadIdx.x;
    float sx = 0.f, sy = 0.f, sz = 0.f;
    for (int i = tid; i < 8192; i += 256) {
        const float* q = xyz + ((size_t)b * 8192 + i) * 3;
        sx += q[0]; sy += q[1]; sz += q[2];
    }
    __shared__ float sh[768];
    sh[tid] = sx; sh[256 + tid] = sy; sh[512 + tid] = sz;
    __syncthreads();
    for (int off = 128; off; off >>= 1) {
        if (tid < off) {
            sh[tid]       += sh[tid + off];
            sh[256 + tid] += sh[256 + tid + off];
            sh[512 + tid] += sh[512 + tid + off];
        }
        __syncthreads();
    }
    if (tid == 0) {
        meanb[b * 3 + 0] = sh[0]   / 8192.f;
        meanb[b * 3 + 1] = sh[256] / 8192.f;
        meanb[b * 3 + 2] = sh[512] / 8192.f;
    }
}

// ---------------- farthest point sampling ------------------------------------
__global__ void __launch_bounds__(1024) fps_kernel(
    const float* __restrict__ xyz, const float* __restrict__ meanb,
    float* __restrict__ nxyz)
{
    const int b = blockIdx.x, tid = threadIdx.x;
    const int N1 = 8193;
    float px[9], py[9], pz[9], dist[9];
#pragma unroll
    for (int j = 0; j < 9; ++j) {
        int p = j * 1024 + tid;
        if (p < N1) {
            if (p == 0) {
                px[j] = meanb[b * 3]; py[j] = meanb[b * 3 + 1]; pz[j] = meanb[b * 3 + 2];
            } else {
                const float* q = xyz + ((size_t)b * 8192 + (p - 1)) * 3;
                px[j] = q[0]; py[j] = q[1]; pz[j] = q[2];
            }
        } else { px[j] = 0.f; py[j] = 0.f; pz[j] = 0.f; }
        dist[j] = 1e10f;
    }
    __shared__ float sc[3];
    __shared__ unsigned long long wred[32];
    __shared__ int sfar;
    int far = 0;
    for (int t = 0; t < 1024; ++t) {
        if ((far & 1023) == tid) {
            int j = far >> 10;
            sc[0] = px[j]; sc[1] = py[j]; sc[2] = pz[j];
            float* o = nxyz + ((size_t)b * 1024 + t) * 3;
            o[0] = px[j]; o[1] = py[j]; o[2] = pz[j];
        }
        __syncthreads();
        float cx = sc[0], cy = sc[1], cz = sc[2];
        unsigned long long best = 0;
#pragma unroll
        for (int j = 0; j < 9; ++j) {
            int p = j * 1024 + tid;
            if (p < N1) {
                float dx = px[j] - cx, dy = py[j] - cy, dz = pz[j] - cz;
                float d = __fadd_rn(__fadd_rn(__fmul_rn(dx, dx), __fmul_rn(dy, dy)),
                                    __fmul_rn(dz, dz));
                float nd = fminf(dist[j], d);
                dist[j] = nd;
                unsigned long long pk =
                    ((unsigned long long)__float_as_uint(nd) << 32) |
                    (unsigned long long)(0xFFFFFFFFu - (unsigned)p);
                if (pk > best) best = pk;
            }
        }
        for (int off = 16; off; off >>= 1) {
            unsigned long long o2 = __shfl_down_sync(0xFFFFFFFFu, best, off);
            if (o2 > best) best = o2;
        }
        if ((tid & 31) == 0) wred[tid >> 5] = best;
        __syncthreads();
        if (tid < 32) {
            best = wred[tid];
            for (int off = 16; off; off >>= 1) {
                unsigned long long o2 = __shfl_down_sync(0xFFFFFFFFu, best, off);
                if (o2 > best) best = o2;
            }
            if (tid == 0)
                sfar = (int)(0xFFFFFFFFu - (unsigned)(best & 0xFFFFFFFFull));
        }
        __syncthreads();
        far = sfar;
    }
}

// ---------------- ball query --------------------------------------------------
__global__ void ball_kernel(const float* __restrict__ xyz,
                            const float* __restrict__ nxyz,
                            int* __restrict__ idx, float r2, int K)
{
    int w = (blockIdx.x * blockDim.x + threadIdx.x) >> 5;
    int lane = threadIdx.x & 31;
    if (w >= 8192) return;
    int b = w >> 10;
    float cx = nxyz[(size_t)w * 3], cy = nxyz[(size_t)w * 3 + 1], cz = nxyz[(size_t)w * 3 + 2];
    const float* X = xyz + (size_t)b * 8192 * 3;
    int cnt = 0, first = 0;
    int* out = idx + (size_t)w * K;
    for (int base = 0; base < 8192; base += 32) {
        int p = base + lane;
        float dx = X[p * 3] - cx, dy = X[p * 3 + 1] - cy, dz = X[p * 3 + 2] - cz;
        float d2 = __fadd_rn(__fadd_rn(__fmul_rn(dx, dx), __fmul_rn(dy, dy)),
                             __fmul_rn(dz, dz));
        bool in = d2 < r2;
        unsigned mask = __ballot_sync(0xFFFFFFFFu, in);
        if (cnt == 0 && mask) first = base + __ffs(mask) - 1;
        if (in) {
            int pos = cnt + __popc(mask & ((1u << lane) - 1u));
            if (pos < K) out[pos] = p;
        }
        cnt += __popc(mask);
        if (cnt >= K) break;
    }
    if (cnt < K) {
        for (int pos = cnt + lane; pos < K; pos += 32) out[pos] = first;
    }
}

// ---------------- gather ------------------------------------------------------
__global__ void gather_kernel(const float* __restrict__ xyz,
                              const float* __restrict__ feat,
                              const float* __restrict__ nxyz,
                              const int* __restrict__ idx,
                              float* __restrict__ X0, int K)
{
    size_t M = (size_t)8192 * K;
    size_t m = (size_t)blockIdx.x * 256 + threadIdx.x;
    if (m >= M) return;
    int k = (int)(m % K);
    int bs = (int)(m / K);
    int b = bs >> 10;
    int p = idx[(size_t)bs * K + k];
    const float* pt = xyz + ((size_t)b * 8192 + p) * 3;
    const float* ct = nxyz + (size_t)bs * 3;
    X0[0 * M + m] = pt[0] - ct[0];
    X0[1 * M + m] = pt[1] - ct[1];
    X0[2 * M + m] = pt[2] - ct[2];
    const float* fb = feat + (size_t)b * 64 * 8192 + p;
#pragma unroll 4
    for (int c = 0; c < 64; ++c)
        X0[(size_t)(3 + c) * M + m] = fb[(size_t)c * 8192];
}

// ---------------- W prep: Wg[k][o] = tf32(W[o][k]), zero-padded to Ipad ------
__global__ void wprep_kernel(const float* __restrict__ W, float* __restrict__ Wg,
                             int O, int I, int Ipad)
{
    int e = blockIdx.x * 256 + threadIdx.x;
    if (e >= Ipad * O) return;
    int k = e / O, o = e % O;
    Wg[e] = (k < I) ? to_tf32(W[(size_t)o * I + k]) : 0.f;
}

// ---------------- pipelined tensor-core GEMM ---------------------------------
// Wg: (Ipad,O) tf32 pre-transposed; X: (I,M) raw fp32; act = relu(aa*x+ad).
// If Y != null: write Y + per-channel sum/sumsq. Else (last layer): per-channel
// sum/sumsq + per (channel, group-of-K) encoded max/min atomics, no Y write.
#define WP 72
#define XP 264
__global__ void __launch_bounds__(256, 2) gemm_tc2_kernel(
    int O, int I, int Ipad, int M, int K,
    const float* __restrict__ Wg, const float* __restrict__ X,
    float* __restrict__ Y,
    const float* __restrict__ aa, const float* __restrict__ ad,
    float* __restrict__ gsum, float* __restrict__ gsq,
    unsigned* __restrict__ emax, unsigned* __restrict__ emin)
{
    extern __shared__ float sm[];
    float* Wt = sm;                          // 2 * 32 * WP
    float* Xt = sm + 2 * 32 * WP;            // 2 * 32 * XP
    float* ssum = sm + 2 * 32 * WP + 2 * 32 * XP;
    float* ssq  = ssum + 64;

    const int tid = threadIdx.x, lane = tid & 31, wid = tid >> 5;
    const int warpO = wid >> 2, warpM = wid & 3;
    const int ob = blockIdx.y * 64, mb = blockIdx.x * 256;
    const int r0 = lane >> 2, kq = lane & 3;
    const int kx = tid >> 6;                 // X-tile row sub-index
    const int c4 = (tid & 63) * 4;           // X-tile col (float4)
    const int NT = Ipad >> 5;

    if (tid < 64) { ssum[tid] = 0.f; ssq[tid] = 0.f; }

    float acc[2][8][4];
#pragma unroll
    for (int r = 0; r < 2; ++r)
#pragma unroll
        for (int nt = 0; nt < 8; ++nt)
#pragma unroll
            for (int c = 0; c < 4; ++c) acc[r][nt][c] = 0.f;

    float4 xr[8];

    // --- lambdas (inlined) ---
    auto ldgX = [&](int t) {
#pragma unroll
        for (int l = 0; l < 8; ++l) {
            int gk = t * 32 + l * 4 + kx;
            if (gk < I) xr[l] = *(const float4*)(X + (size_t)gk * M + mb + c4);
            else        xr[l] = make_float4(0.f, 0.f, 0.f, 0.f);
        }
    };
    auto stsX = [&](int t, int st) {
        float* Xs = Xt + st * (32 * XP);
#pragma unroll
        for (int l = 0; l < 8; ++l) {
            int k = l * 4 + kx;
            float4 v = xr[l];
            if (aa) {
                int gk = t * 32 + k;
                float A_ = aa[gk], D_ = ad[gk];
                v.x = fmaxf(v.x * A_ + D_, 0.f);
                v.y = fmaxf(v.y * A_ + D_, 0.f);
                v.z = fmaxf(v.z * A_ + D_, 0.f);
                v.w = fmaxf(v.w * A_ + D_, 0.f);
            }
            Xs[k * XP + c4 + 0] = to_tf32(v.x);
            Xs[k * XP + c4 + 1] = to_tf32(v.y);
            Xs[k * XP + c4 + 2] = to_tf32(v.z);
            Xs[k * XP + c4 + 3] = to_tf32(v.w);
        }
    };
    auto cpW = [&](int t, int st) {
        float* Ws = Wt + st * (32 * WP);
#pragma unroll
        for (int l = 0; l < 2; ++l) {
            int e = l * 256 + tid;
            int k = e >> 4, o4 = (e & 15) * 4;
            cp16(&Ws[k * WP + o4], Wg + (size_t)(t * 32 + k) * O + ob + o4);
        }
    };

    // --- prologue ---
    ldgX(0);
    cpW(0, 0);
    asm volatile("cp.async.commit_group;\n");
    asm volatile("cp.async.wait_group 0;\n");
    stsX(0, 0);
    if (NT > 1) ldgX(1);
    __syncthreads();

    // --- main pipeline ---
    for (int t = 0; t < NT; ++t) {
        int cur = t & 1, nxt = cur ^ 1;
        if (t + 1 < NT) {
            stsX(t + 1, nxt);
            cpW(t + 1, nxt);
            asm volatile("cp.async.commit_group;\n");
        }
        if (t + 2 < NT) ldgX(t + 2);

        const float* Wc = Wt + cur * (32 * WP);
        const float* Xc = Xt + cur * (32 * XP);
#pragma unroll
        for (int k8 = 0; k8 < 4; ++k8) {
            int kb = k8 * 8;
            uint32_t afr[2][4], bfr[8][2];
#pragma unroll
            for (int r = 0; r < 2; ++r) {
                int o = warpO * 32 + r * 16 + r0;
                afr[r][0] = __float_as_uint(Wc[(kb + kq) * WP + o]);
                afr[r][1] = __float_as_uint(Wc[(kb + kq) * WP + o + 8]);
                afr[r][2] = __float_as_uint(Wc[(kb + kq + 4) * WP + o]);
                afr[r][3] = __float_as_uint(Wc[(kb + kq + 4) * WP + o + 8]);
            }
#pragma unroll
            for (int nt = 0; nt < 8; ++nt) {
                int m = warpM * 64 + nt * 8 + r0;
                bfr[nt][0] = __float_as_uint(Xc[(kb + kq) * XP + m]);
                bfr[nt][1] = __float_as_uint(Xc[(kb + kq + 4) * XP + m]);
            }
#pragma unroll
            for (int r = 0; r < 2; ++r)
#pragma unroll
                for (int nt = 0; nt < 8; ++nt)
                    mma_tf32(acc[r][nt], afr[r], bfr[nt]);
        }
        if (t + 1 < NT) asm volatile("cp.async.wait_group 0;\n");
        __syncthreads();
    }

    // --- epilogue ---
#pragma unroll
    for (int r = 0; r < 2; ++r) {
#pragma unroll
        for (int half = 0; half < 2; ++half) {
            int ol = warpO * 32 + r * 16 + r0 + half * 8;
            float s = 0.f, q = 0.f;
            if (Y) {
                size_t rowoff = (size_t)(ob + ol) * M + mb + warpM * 64 + kq * 2;
#pragma unroll
                for (int nt = 0; nt < 8; ++nt) {
                    float v0 = acc[r][nt][half * 2 + 0];
                    float v1 = acc[r][nt][half * 2 + 1];
                    *(float2*)(Y + rowoff + nt * 8) = make_float2(v0, v1);
                    s += v0 + v1;
                    q += v0 * v0 + v1 * v1;
                }
            } else {
                int ntg = K >> 3;   // nt tiles per sample-group
                for (int g0 = 0; g0 < 8; g0 += ntg) {
                    float mxv = -3.4e38f, mnv = 3.4e38f;
                    for (int nt = g0; nt < g0 + ntg; ++nt) {
                        float v0 = acc[r][nt][half * 2 + 0];
                        float v1 = acc[r][nt][half * 2 + 1];
                        s += v0 + v1;
                        q += v0 * v0 + v1 * v1;
                        mxv = fmaxf(mxv, fmaxf(v0, v1));
                        mnv = fminf(mnv, fminf(v0, v1));
                    }
                    mxv = fmaxf(mxv, __shfl_xor_sync(0xFFFFFFFFu, mxv, 1));
                    mnv = fminf(mnv, __shfl_xor_sync(0xFFFFFFFFu, mnv, 1));
                    mxv = fmaxf(mxv, __shfl_xor_sync(0xFFFFFFFFu, mxv, 2));
                    mnv = fminf(mnv, __shfl_xor_sync(0xFFFFFFFFu, mnv, 2));
                    if (kq == 0) {
                        int bs = (mb + warpM * 64 + g0 * 8) / K;
                        atomicMax(&emax[(size_t)(ob + ol) * 8192 + bs], encf(mxv));
                        atomicMax(&emin[(size_t)(ob + ol) * 8192 + bs], encf(-mnv));
                    }
                }
            }
            s += __shfl_xor_sync(0xFFFFFFFFu, s, 1);
            q += __shfl_xor_sync(0xFFFFFFFFu, q, 1);
            s += __shfl_xor_sync(0xFFFFFFFFu, s, 2);
            q += __shfl_xor_sync(0xFFFFFFFFu, q, 2);
            if (kq == 0) {
                atomicAdd(&ssum[ol], s);
                atomicAdd(&ssq[ol], q);
            }
        }
    }
    __syncthreads();
    if (tid < 64) {
        atomicAdd(&gsum[ob + tid], ssum[tid]);
        atomicAdd(&gsq[ob + tid], ssq[tid]);
    }
}

// ---------------- BN finalize -------------------------------------------------
__global__ void finalize_kernel(float* __restrict__ sum, float* __restrict__ sq,
                                const float* __restrict__ g, const float* __restrict__ bb,
                                float* __restrict__ aa, float* __restrict__ ad,
                                int O, float invn)
{
    int c = threadIdx.x;
    if (c < O) {
        float m = sum[c] * invn;
        float v = sq[c] * invn - m * m;
        float a = g[c] / sqrtf(v + 1e-5f);
        aa[c] = a;
        ad[c] = bb[c] - m * a;
    }
    if (c < 256) { sum[c] = 0.f; sq[c] = 0.f; }
}

__global__ void zero_stats_kernel(float* __restrict__ s, float* __restrict__ q)
{
    int t = threadIdx.x;
    if (t < 256) { s[t] = 0.f; q[t] = 0.f; }
}

// ---------------- final: decode max/min, apply last affine+relu --------------
__global__ void maxfin_kernel(const unsigned* __restrict__ emax,
                              const unsigned* __restrict__ emin,
                              const float* __restrict__ aa, const float* __restrict__ ad,
                              float* __restrict__ out, int O, int coff)
{
    int gid = blockIdx.x * blockDim.x + threadIdx.x;
    int total = 8 * O * 1024;
    if (gid >= total) return;
    int s = gid & 1023;
    int c = (gid >> 10) % O;
    int b = gid / (O * 1024);
    int bs = b * 1024 + s;
    float a = aa[c], d = ad[c];
    float y = (a >= 0.f) ? decf(emax[(size_t)c * 8192 + bs])
                         : -decf(emin[(size_t)c * 8192 + bs]);
    out[((size_t)b * 384 + coff + c) * 1024 + s] = fmaxf(y * a + d, 0.f);
}

// ---------------- host launch ------------------------------------------------
extern "C" void kernel_launch(void* const* d_in, const int* in_sizes, int n_in,
                              void* d_out, int out_size)
{
    (void)in_sizes; (void)n_in; (void)out_size;
    const float* xyz  = (const float*)d_in[0];
    const float* feat = (const float*)d_in[1];
    const float* W[2][3]; const float* G[2][3]; const float* Bb[2][3];
    for (int bi = 0; bi < 2; ++bi)
        for (int li = 0; li < 3; ++li) {
            W[bi][li]  = (const float*)d_in[2 + bi * 9 + li * 3 + 0];
            G[bi][li]  = (const float*)d_in[2 + bi * 9 + li * 3 + 1];
            Bb[bi][li] = (const float*)d_in[2 + bi * 9 + li * 3 + 2];
        }
    float* out      = (float*)d_out;
    float* nxyz     = out;            // (8,1024,3)
    float* feat_out = out + 24576;    // (8,384,1024)

    float *bufA, *bufB, *meanb, *sum, *sq, *aa, *ad, *wt; int* idxb;
    unsigned *emax, *emin;
    cudaGetSymbolAddress((void**)&bufA, g_bufA);
    cudaGetSymbolAddress((void**)&bufB, g_bufB);
    cudaGetSymbolAddress((void**)&meanb, g_meanb);
    cudaGetSymbolAddress((void**)&idxb, g_idxb);
    cudaGetSymbolAddress((void**)&sum, g_sum);
    cudaGetSymbolAddress((void**)&sq, g_sq);
    cudaGetSymbolAddress((void**)&aa, g_affa);
    cudaGetSymbolAddress((void**)&ad, g_affd);
    cudaGetSymbolAddress((void**)&wt, g_wt);
    cudaGetSymbolAddress((void**)&emax, g_emax);
    cudaGetSymbolAddress((void**)&emin, g_emin);

    const int SMEM_GEMM = (2 * 32 * WP + 2 * 32 * XP + 128) * 4;  // 86528 B
    cudaFuncSetAttribute(gemm_tc2_kernel,
                         cudaFuncAttributeMaxDynamicSharedMemorySize, SMEM_GEMM);

    const int OS[2][4] = { {67, 64, 64, 128}, {67, 64, 128, 256} };
    const int KS[2] = {32, 64};
    const float R2[2] = { (float)(0.4 * 0.4), (float)(0.8 * 0.8) };
    // per-layer padded-I, and offsets into g_wt
    int IP[2][3], WOFF[2][3];
    {
        int off = 0;
        for (int bi = 0; bi < 2; ++bi)
            for (int li = 0; li < 3; ++li) {
                int I = OS[bi][li], O = OS[bi][li + 1];
                int Ipad = (I + 31) & ~31;
                IP[bi][li] = Ipad;
                WOFF[bi][li] = off;
                off += Ipad * O;
            }
    }

    // weight prep (independent of everything else)
    for (int bi = 0; bi < 2; ++bi)
        for (int li = 0; li < 3; ++li) {
            int I = OS[bi][li], O = OS[bi][li + 1], Ipad = IP[bi][li];
            wprep_kernel<<<(Ipad * O + 255) / 256, 256>>>(W[bi][li], wt + WOFF[bi][li],
                                                          O, I, Ipad);
        }

    mean_kernel<<<8, 256>>>(xyz, meanb);
    fps_kernel<<<8, 1024>>>(xyz, meanb, nxyz);
    zero_stats_kernel<<<1, 256>>>(sum, sq);

    for (int bi = 0; bi < 2; ++bi) {
        int K = KS[bi];
        int M = 8192 * K;
        float invn = 1.0f / (float)M;

        ball_kernel<<<2048, 128>>>(xyz, nxyz, idxb, R2[bi], K);
        gather_kernel<<<(M + 255) / 256, 256>>>(xyz, feat, nxyz, idxb, bufA, K);

        // L0: (O1 x 67) * X0 -> bufB
        {
            dim3 grid(M / 256, OS[bi][1] / 64);
            gemm_tc2_kernel<<<grid, 256, SMEM_GEMM>>>(
                OS[bi][1], OS[bi][0], IP[bi][0], M, K, wt + WOFF[bi][0],
                bufA, bufB, nullptr, nullptr, sum, sq, nullptr, nullptr);
            finalize_kernel<<<1, 256>>>(sum, sq, G[bi][0], Bb[bi][0], aa, ad, OS[bi][1], invn);
        }
        // L1: (O2 x O1) * act(bufB) -> bufA
        {
            dim3 grid(M / 256, OS[bi][2] / 64);
            gemm_tc2_kernel<<<grid, 256, SMEM_GEMM>>>(
                OS[bi][2], OS[bi][1], IP[bi][1], M, K, wt + WOFF[bi][1],
                bufB, bufA, aa, ad, sum, sq, nullptr, nullptr);
            finalize_kernel<<<1, 256>>>(sum, sq, G[bi][1], Bb[bi][1], aa, ad, OS[bi][2], invn);
        }
        // L2: (O3 x O2) * act(bufA) -> fused max/min epilogue (no Y write)
        {
            cudaMemsetAsync(emax, 0, (size_t)OS[bi][3] * 8192 * 4, 0);
            cudaMemsetAsync(emin, 0, (size_t)OS[bi][3] * 8192 * 4, 0);
            dim3 grid(M / 256, OS[bi][3] / 64);
            gemm_tc2_kernel<<<grid, 256, SMEM_GEMM>>>(
                OS[bi][3], OS[bi][2], IP[bi][2], M, K, wt + WOFF[bi][2],
                bufA, nullptr, aa, ad, sum, sq, emax, emin);
            finalize_kernel<<<1, 256>>>(sum, sq, G[bi][2], Bb[bi][2], aa, ad, OS[bi][3], invn);
        }
        // decode + final affine + relu -> output
        {
            int total = 8 * OS[bi][3] * 1024;
            maxfin_kernel<<<(total + 255) / 256, 256>>>(emax, emin, aa, ad, feat_out,
                                                        OS[bi][3], bi == 0 ? 0 : 128);
        }
    }
}

// round 8
// speedup vs baseline: 1.7663x; 1.0270x over previous
#include <cuda_runtime.h>
#include <cstdint>
#include <cstddef>

// ---------------- scratch (static device memory; no allocs allowed) ----------
static __device__ float g_bufA[(size_t)128 * 524288];   // 256 MB
static __device__ float g_bufB[(size_t)128 * 524288];   // 256 MB
static __device__ float g_featT[(size_t)8 * 8192 * 64]; // 16 MB transposed features
static __device__ float g_meanb[24];
static __device__ int   g_idxb[8 * 1024 * 64];
static __device__ float g_sum[256];
static __device__ float g_sq[256];
static __device__ float g_affa[256];
static __device__ float g_affd[256];
static __device__ float g_wt[65536];                    // pre-transposed tf32 weights
static __device__ unsigned g_emax[256 * 8192];          // encoded max
static __device__ unsigned g_emin[256 * 8192];          // encoded max of -y

// ---------------- helpers ----------------------------------------------------
__device__ __forceinline__ float to_tf32(float x)
{
    uint32_t r;
    asm volatile("cvt.rna.tf32.f32 %0, %1;\n" : "=r"(r) : "f"(x));
    return __uint_as_float(r);
}
__device__ __forceinline__ void mma_tf32(float* d, const uint32_t* a, const uint32_t* b)
{
    asm volatile(
        "mma.sync.aligned.m16n8k8.row.col.f32.tf32.tf32.f32 "
        "{%0,%1,%2,%3}, {%4,%5,%6,%7}, {%8,%9}, {%0,%1,%2,%3};\n"
        : "+f"(d[0]), "+f"(d[1]), "+f"(d[2]), "+f"(d[3])
        : "r"(a[0]), "r"(a[1]), "r"(a[2]), "r"(a[3]),
          "r"(b[0]), "r"(b[1]));
}
__device__ __forceinline__ void cp16(void* dst, const void* src)
{
    uint32_t d = (uint32_t)__cvta_generic_to_shared(dst);
    asm volatile("cp.async.ca.shared.global [%0], [%1], 16;\n" :: "r"(d), "l"(src));
}
__device__ __forceinline__ unsigned encf(float f)
{
    unsigned u = __float_as_uint(f);
    return (u >> 31) ? ~u : (u | 0x80000000u);
}
__device__ __forceinline__ float decf(unsigned u)
{
    return __uint_as_float((u >> 31) ? (u & 0x7FFFFFFFu) : ~u);
}

// ---------------- mean over N of xyz ----------------------------------------
__global__ void mean_kernel(const float* __restrict__ xyz, float* __restrict__ meanb)
{
    int b = blockIdx.x, tid = threadIdx.x;
    float sx = 0.f, sy = 0.f, sz = 0.f;
    for (int i = tid; i < 8192; i += 256) {
        const float* q = xyz + ((size_t)b * 8192 + i) * 3;
        sx += q[0]; sy += q[1]; sz += q[2];
    }
    __shared__ float sh[768];
    sh[tid] = sx; sh[256 + tid] = sy; sh[512 + tid] = sz;
    __syncthreads();
    for (int off = 128; off; off >>= 1) {
        if (tid < off) {
            sh[tid]       += sh[tid + off];
            sh[256 + tid] += sh[256 + tid + off];
            sh[512 + tid] += sh[512 + tid + off];
        }
        __syncthreads();
    }
    if (tid == 0) {
        meanb[b * 3 + 0] = sh[0]   / 8192.f;
        meanb[b * 3 + 1] = sh[256] / 8192.f;
        meanb[b * 3 + 2] = sh[512] / 8192.f;
    }
}

// ---------------- feature transpose: feat (B,C,N) -> featT (B,N,C) ----------
__global__ void feat_transpose_kernel(const float* __restrict__ feat,
                                      float* __restrict__ featT)
{
    __shared__ float tile[32][33];
    int b = blockIdx.z;
    int p0 = blockIdx.x * 32;   // N dim
    int c0 = blockIdx.y * 32;   // C dim
    int tx = threadIdx.x, ty = threadIdx.y;   // 32 x 8
#pragma unroll
    for (int i = ty; i < 32; i += 8)
        tile[i][tx] = feat[((size_t)b * 64 + c0 + i) * 8192 + p0 + tx];
    __syncthreads();
#pragma unroll
    for (int i = ty; i < 32; i += 8)
        featT[((size_t)b * 8192 + p0 + i) * 64 + c0 + tx] = tile[tx][i];
}

// ---------------- farthest point sampling ------------------------------------
__global__ void __launch_bounds__(1024) fps_kernel(
    const float* __restrict__ xyz, const float* __restrict__ meanb,
    float* __restrict__ nxyz)
{
    const int b = blockIdx.x, tid = threadIdx.x;
    const int N1 = 8193;
    float px[9], py[9], pz[9], dist[9];
#pragma unroll
    for (int j = 0; j < 9; ++j) {
        int p = j * 1024 + tid;
        if (p < N1) {
            if (p == 0) {
                px[j] = meanb[b * 3]; py[j] = meanb[b * 3 + 1]; pz[j] = meanb[b * 3 + 2];
            } else {
                const float* q = xyz + ((size_t)b * 8192 + (p - 1)) * 3;
                px[j] = q[0]; py[j] = q[1]; pz[j] = q[2];
            }
        } else { px[j] = 0.f; py[j] = 0.f; pz[j] = 0.f; }
        dist[j] = 1e10f;
    }
    __shared__ float sc[3];
    __shared__ unsigned long long wred[32];
    __shared__ int sfar;
    int far = 0;
    for (int t = 0; t < 1024; ++t) {
        if ((far & 1023) == tid) {
            int j = far >> 10;
            sc[0] = px[j]; sc[1] = py[j]; sc[2] = pz[j];
            float* o = nxyz + ((size_t)b * 1024 + t) * 3;
            o[0] = px[j]; o[1] = py[j]; o[2] = pz[j];
        }
        __syncthreads();
        float cx = sc[0], cy = sc[1], cz = sc[2];
        unsigned long long best = 0;
#pragma unroll
        for (int j = 0; j < 9; ++j) {
            int p = j * 1024 + tid;
            if (p < N1) {
                float dx = px[j] - cx, dy = py[j] - cy, dz = pz[j] - cz;
                float d = __fadd_rn(__fadd_rn(__fmul_rn(dx, dx), __fmul_rn(dy, dy)),
                                    __fmul_rn(dz, dz));
                float nd = fminf(dist[j], d);
                dist[j] = nd;
                unsigned long long pk =
                    ((unsigned long long)__float_as_uint(nd) << 32) |
                    (unsigned long long)(0xFFFFFFFFu - (unsigned)p);
                if (pk > best) best = pk;
            }
        }
        for (int off = 16; off; off >>= 1) {
            unsigned long long o2 = __shfl_down_sync(0xFFFFFFFFu, best, off);
            if (o2 > best) best = o2;
        }
        if ((tid & 31) == 0) wred[tid >> 5] = best;
        __syncthreads();
        if (tid < 32) {
            best = wred[tid];
            for (int off = 16; off; off >>= 1) {
                unsigned long long o2 = __shfl_down_sync(0xFFFFFFFFu, best, off);
                if (o2 > best) best = o2;
            }
            if (tid == 0)
                sfar = (int)(0xFFFFFFFFu - (unsigned)(best & 0xFFFFFFFFull));
        }
        __syncthreads();
        far = sfar;
    }
}

// ---------------- ball query --------------------------------------------------
__global__ void ball_kernel(const float* __restrict__ xyz,
                            const float* __restrict__ nxyz,
                            int* __restrict__ idx, float r2, int K)
{
    int w = (blockIdx.x * blockDim.x + threadIdx.x) >> 5;
    int lane = threadIdx.x & 31;
    if (w >= 8192) return;
    int b = w >> 10;
    float cx = nxyz[(size_t)w * 3], cy = nxyz[(size_t)w * 3 + 1], cz = nxyz[(size_t)w * 3 + 2];
    const float* X = xyz + (size_t)b * 8192 * 3;
    int cnt = 0, first = 0;
    int* out = idx + (size_t)w * K;
    for (int base = 0; base < 8192; base += 32) {
        int p = base + lane;
        float dx = X[p * 3] - cx, dy = X[p * 3 + 1] - cy, dz = X[p * 3 + 2] - cz;
        float d2 = __fadd_rn(__fadd_rn(__fmul_rn(dx, dx), __fmul_rn(dy, dy)),
                             __fmul_rn(dz, dz));
        bool in = d2 < r2;
        unsigned mask = __ballot_sync(0xFFFFFFFFu, in);
        if (cnt == 0 && mask) first = base + __ffs(mask) - 1;
        if (in) {
            int pos = cnt + __popc(mask & ((1u << lane) - 1u));
            if (pos < K) out[pos] = p;
        }
        cnt += __popc(mask);
        if (cnt >= K) break;
    }
    if (cnt < K) {
        for (int pos = cnt + lane; pos < K; pos += 32) out[pos] = first;
    }
}

// ---------------- gather (featT: contiguous 64-ch reads per point) -----------
__global__ void gather_kernel(const float* __restrict__ xyz,
                              const float* __restrict__ featT,
                              const float* __restrict__ nxyz,
                              const int* __restrict__ idx,
                              float* __restrict__ X0, int K)
{
    size_t M = (size_t)8192 * K;
    size_t m = (size_t)blockIdx.x * 256 + threadIdx.x;
    if (m >= M) return;
    int k = (int)(m % K);
    int bs = (int)(m / K);
    int b = bs >> 10;
    int p = idx[(size_t)bs * K + k];
    const float* pt = xyz + ((size_t)b * 8192 + p) * 3;
    const float* ct = nxyz + (size_t)bs * 3;
    X0[0 * M + m] = pt[0] - ct[0];
    X0[1 * M + m] = pt[1] - ct[1];
    X0[2 * M + m] = pt[2] - ct[2];
    const float* fb = featT + ((size_t)b * 8192 + p) * 64;
#pragma unroll
    for (int c = 0; c < 64; c += 4) {
        float4 v = *(const float4*)(fb + c);
        X0[(size_t)(3 + c)     * M + m] = v.x;
        X0[(size_t)(3 + c + 1) * M + m] = v.y;
        X0[(size_t)(3 + c + 2) * M + m] = v.z;
        X0[(size_t)(3 + c + 3) * M + m] = v.w;
    }
}

// ---------------- W prep: Wg[k][o] = tf32(W[o][k]), zero-padded to Ipad ------
__global__ void wprep_kernel(const float* __restrict__ W, float* __restrict__ Wg,
                             int O, int I, int Ipad)
{
    int e = blockIdx.x * 256 + threadIdx.x;
    if (e >= Ipad * O) return;
    int k = e / O, o = e % O;
    Wg[e] = (k < I) ? to_tf32(W[(size_t)o * I + k]) : 0.f;
}

// ---------------- pipelined tensor-core GEMM ---------------------------------
// grid.x = O/64 (fastest-varying -> same-mb blocks co-resident, X reuse in L2)
// grid.y = M/256
#define WP 72
#define XP 264
__global__ void __launch_bounds__(256, 2) gemm_tc2_kernel(
    int O, int I, int Ipad, int M, int K,
    const float* __restrict__ Wg, const float* __restrict__ X,
    float* __restrict__ Y,
    const float* __restrict__ aa, const float* __restrict__ ad,
    float* __restrict__ gsum, float* __restrict__ gsq,
    unsigned* __restrict__ emax, unsigned* __restrict__ emin)
{
    extern __shared__ float sm[];
    float* Wt = sm;                          // 2 * 32 * WP
    float* Xt = sm + 2 * 32 * WP;            // 2 * 32 * XP
    float* ssum = sm + 2 * 32 * WP + 2 * 32 * XP;
    float* ssq  = ssum + 64;

    const int tid = threadIdx.x, lane = tid & 31, wid = tid >> 5;
    const int warpO = wid >> 2, warpM = wid & 3;
    const int ob = blockIdx.x * 64, mb = blockIdx.y * 256;
    const int r0 = lane >> 2, kq = lane & 3;
    const int kx = tid >> 6;
    const int c4 = (tid & 63) * 4;
    const int NT = Ipad >> 5;

    if (tid < 64) { ssum[tid] = 0.f; ssq[tid] = 0.f; }

    float acc[2][8][4];
#pragma unroll
    for (int r = 0; r < 2; ++r)
#pragma unroll
        for (int nt = 0; nt < 8; ++nt)
#pragma unroll
            for (int c = 0; c < 4; ++c) acc[r][nt][c] = 0.f;

    float4 xr[8];

    auto ldgX = [&](int t) {
#pragma unroll
        for (int l = 0; l < 8; ++l) {
            int gk = t * 32 + l * 4 + kx;
            if (gk < I) xr[l] = *(const float4*)(X + (size_t)gk * M + mb + c4);
            else        xr[l] = make_float4(0.f, 0.f, 0.f, 0.f);
        }
    };
    auto stsX = [&](int t, int st) {
        float* Xs = Xt + st * (32 * XP);
#pragma unroll
        for (int l = 0; l < 8; ++l) {
            int k = l * 4 + kx;
            float4 v = xr[l];
            if (aa) {
                int gk = t * 32 + k;
                float A_ = aa[gk], D_ = ad[gk];
                v.x = fmaxf(v.x * A_ + D_, 0.f);
                v.y = fmaxf(v.y * A_ + D_, 0.f);
                v.z = fmaxf(v.z * A_ + D_, 0.f);
                v.w = fmaxf(v.w * A_ + D_, 0.f);
            }
            Xs[k * XP + c4 + 0] = to_tf32(v.x);
            Xs[k * XP + c4 + 1] = to_tf32(v.y);
            Xs[k * XP + c4 + 2] = to_tf32(v.z);
            Xs[k * XP + c4 + 3] = to_tf32(v.w);
        }
    };
    auto cpW = [&](int t, int st) {
        float* Ws = Wt + st * (32 * WP);
#pragma unroll
        for (int l = 0; l < 2; ++l) {
            int e = l * 256 + tid;
            int k = e >> 4, o4 = (e & 15) * 4;
            cp16(&Ws[k * WP + o4], Wg + (size_t)(t * 32 + k) * O + ob + o4);
        }
    };

    ldgX(0);
    cpW(0, 0);
    asm volatile("cp.async.commit_group;\n");
    asm volatile("cp.async.wait_group 0;\n");
    stsX(0, 0);
    if (NT > 1) ldgX(1);
    __syncthreads();

    for (int t = 0; t < NT; ++t) {
        int cur = t & 1, nxt = cur ^ 1;
        if (t + 1 < NT) {
            stsX(t + 1, nxt);
            cpW(t + 1, nxt);
            asm volatile("cp.async.commit_group;\n");
        }
        if (t + 2 < NT) ldgX(t + 2);

        const float* Wc = Wt + cur * (32 * WP);
        const float* Xc = Xt + cur * (32 * XP);
#pragma unroll
        for (int k8 = 0; k8 < 4; ++k8) {
            int kb = k8 * 8;
            uint32_t afr[2][4], bfr[8][2];
#pragma unroll
            for (int r = 0; r < 2; ++r) {
                int o = warpO * 32 + r * 16 + r0;
                afr[r][0] = __float_as_uint(Wc[(kb + kq) * WP + o]);
                afr[r][1] = __float_as_uint(Wc[(kb + kq) * WP + o + 8]);
                afr[r][2] = __float_as_uint(Wc[(kb + kq + 4) * WP + o]);
                afr[r][3] = __float_as_uint(Wc[(kb + kq + 4) * WP + o + 8]);
            }
#pragma unroll
            for (int nt = 0; nt < 8; ++nt) {
                int m = warpM * 64 + nt * 8 + r0;
                bfr[nt][0] = __float_as_uint(Xc[(kb + kq) * XP + m]);
                bfr[nt][1] = __float_as_uint(Xc[(kb + kq + 4) * XP + m]);
            }
#pragma unroll
            for (int r = 0; r < 2; ++r)
#pragma unroll
                for (int nt = 0; nt < 8; ++nt)
                    mma_tf32(acc[r][nt], afr[r], bfr[nt]);
        }
        if (t + 1 < NT) asm volatile("cp.async.wait_group 0;\n");
        __syncthreads();
    }

    // --- epilogue ---
#pragma unroll
    for (int r = 0; r < 2; ++r) {
#pragma unroll
        for (int half = 0; half < 2; ++half) {
            int ol = warpO * 32 + r * 16 + r0 + half * 8;
            float s = 0.f, q = 0.f;
            if (Y) {
                size_t rowoff = (size_t)(ob + ol) * M + mb + warpM * 64 + kq * 2;
#pragma unroll
                for (int nt = 0; nt < 8; ++nt) {
                    float v0 = acc[r][nt][half * 2 + 0];
                    float v1 = acc[r][nt][half * 2 + 1];
                    *(float2*)(Y + rowoff + nt * 8) = make_float2(v0, v1);
                    s += v0 + v1;
                    q += v0 * v0 + v1 * v1;
                }
            } else {
                int ntg = K >> 3;
                for (int g0 = 0; g0 < 8; g0 += ntg) {
                    float mxv = -3.4e38f, mnv = 3.4e38f;
                    for (int nt = g0; nt < g0 + ntg; ++nt) {
                        float v0 = acc[r][nt][half * 2 + 0];
                        float v1 = acc[r][nt][half * 2 + 1];
                        s += v0 + v1;
                        q += v0 * v0 + v1 * v1;
                        mxv = fmaxf(mxv, fmaxf(v0, v1));
                        mnv = fminf(mnv, fminf(v0, v1));
                    }
                    mxv = fmaxf(mxv, __shfl_xor_sync(0xFFFFFFFFu, mxv, 1));
                    mnv = fminf(mnv, __shfl_xor_sync(0xFFFFFFFFu, mnv, 1));
                    mxv = fmaxf(mxv, __shfl_xor_sync(0xFFFFFFFFu, mxv, 2));
                    mnv = fminf(mnv, __shfl_xor_sync(0xFFFFFFFFu, mnv, 2));
                    if (kq == 0) {
                        int bs = (mb + warpM * 64 + g0 * 8) / K;
                        atomicMax(&emax[(size_t)(ob + ol) * 8192 + bs], encf(mxv));
                        atomicMax(&emin[(size_t)(ob + ol) * 8192 + bs], encf(-mnv));
                    }
                }
            }
            s += __shfl_xor_sync(0xFFFFFFFFu, s, 1);
            q += __shfl_xor_sync(0xFFFFFFFFu, q, 1);
            s += __shfl_xor_sync(0xFFFFFFFFu, s, 2);
            q += __shfl_xor_sync(0xFFFFFFFFu, q, 2);
            if (kq == 0) {
                atomicAdd(&ssum[ol], s);
                atomicAdd(&ssq[ol], q);
            }
        }
    }
    __syncthreads();
    if (tid < 64) {
        atomicAdd(&gsum[ob + tid], ssum[tid]);
        atomicAdd(&gsq[ob + tid], ssq[tid]);
    }
}

// ---------------- BN finalize -------------------------------------------------
__global__ void finalize_kernel(float* __restrict__ sum, float* __restrict__ sq,
                                const float* __restrict__ g, const float* __restrict__ bb,
                                float* __restrict__ aa, float* __restrict__ ad,
                                int O, float invn)
{
    int c = threadIdx.x;
    if (c < O) {
        float m = sum[c] * invn;
        float v = sq[c] * invn - m * m;
        float a = g[c] / sqrtf(v + 1e-5f);
        aa[c] = a;
        ad[c] = bb[c] - m * a;
    }
    if (c < 256) { sum[c] = 0.f; sq[c] = 0.f; }
}

__global__ void zero_stats_kernel(float* __restrict__ s, float* __restrict__ q)
{
    int t = threadIdx.x;
    if (t < 256) { s[t] = 0.f; q[t] = 0.f; }
}

// ---------------- final: decode max/min, apply last affine+relu --------------
__global__ void maxfin_kernel(const unsigned* __restrict__ emax,
                              const unsigned* __restrict__ emin,
                              const float* __restrict__ aa, const float* __restrict__ ad,
                              float* __restrict__ out, int O, int coff)
{
    int gid = blockIdx.x * blockDim.x + threadIdx.x;
    int total = 8 * O * 1024;
    if (gid >= total) return;
    int s = gid & 1023;
    int c = (gid >> 10) % O;
    int b = gid / (O * 1024);
    int bs = b * 1024 + s;
    float a = aa[c], d = ad[c];
    float y = (a >= 0.f) ? decf(emax[(size_t)c * 8192 + bs])
                         : -decf(emin[(size_t)c * 8192 + bs]);
    out[((size_t)b * 384 + coff + c) * 1024 + s] = fmaxf(y * a + d, 0.f);
}

// ---------------- host launch ------------------------------------------------
extern "C" void kernel_launch(void* const* d_in, const int* in_sizes, int n_in,
                              void* d_out, int out_size)
{
    (void)in_sizes; (void)n_in; (void)out_size;
    const float* xyz  = (const float*)d_in[0];
    const float* feat = (const float*)d_in[1];
    const float* W[2][3]; const float* G[2][3]; const float* Bb[2][3];
    for (int bi = 0; bi < 2; ++bi)
        for (int li = 0; li < 3; ++li) {
            W[bi][li]  = (const float*)d_in[2 + bi * 9 + li * 3 + 0];
            G[bi][li]  = (const float*)d_in[2 + bi * 9 + li * 3 + 1];
            Bb[bi][li] = (const float*)d_in[2 + bi * 9 + li * 3 + 2];
        }
    float* out      = (float*)d_out;
    float* nxyz     = out;            // (8,1024,3)
    float* feat_out = out + 24576;    // (8,384,1024)

    float *bufA, *bufB, *featT, *meanb, *sum, *sq, *aa, *ad, *wt; int* idxb;
    unsigned *emax, *emin;
    cudaGetSymbolAddress((void**)&bufA, g_bufA);
    cudaGetSymbolAddress((void**)&bufB, g_bufB);
    cudaGetSymbolAddress((void**)&featT, g_featT);
    cudaGetSymbolAddress((void**)&meanb, g_meanb);
    cudaGetSymbolAddress((void**)&idxb, g_idxb);
    cudaGetSymbolAddress((void**)&sum, g_sum);
    cudaGetSymbolAddress((void**)&sq, g_sq);
    cudaGetSymbolAddress((void**)&aa, g_affa);
    cudaGetSymbolAddress((void**)&ad, g_affd);
    cudaGetSymbolAddress((void**)&wt, g_wt);
    cudaGetSymbolAddress((void**)&emax, g_emax);
    cudaGetSymbolAddress((void**)&emin, g_emin);

    const int SMEM_GEMM = (2 * 32 * WP + 2 * 32 * XP + 128) * 4;  // 86528 B
    cudaFuncSetAttribute(gemm_tc2_kernel,
                         cudaFuncAttributeMaxDynamicSharedMemorySize, SMEM_GEMM);

    const int OS[2][4] = { {67, 64, 64, 128}, {67, 64, 128, 256} };
    const int KS[2] = {32, 64};
    const float R2[2] = { (float)(0.4 * 0.4), (float)(0.8 * 0.8) };
    int IP[2][3], WOFF[2][3];
    {
        int off = 0;
        for (int bi = 0; bi < 2; ++bi)
            for (int li = 0; li < 3; ++li) {
                int I = OS[bi][li], O = OS[bi][li + 1];
                int Ipad = (I + 31) & ~31;
                IP[bi][li] = Ipad;
                WOFF[bi][li] = off;
                off += Ipad * O;
            }
    }

    for (int bi = 0; bi < 2; ++bi)
        for (int li = 0; li < 3; ++li) {
            int I = OS[bi][li], O = OS[bi][li + 1], Ipad = IP[bi][li];
            wprep_kernel<<<(Ipad * O + 255) / 256, 256>>>(W[bi][li], wt + WOFF[bi][li],
                                                          O, I, Ipad);
        }

    {
        dim3 tg(256, 2, 8), tb(32, 8);
        feat_transpose_kernel<<<tg, tb>>>(feat, featT);
    }
    mean_kernel<<<8, 256>>>(xyz, meanb);
    fps_kernel<<<8, 1024>>>(xyz, meanb, nxyz);
    zero_stats_kernel<<<1, 256>>>(sum, sq);

    for (int bi = 0; bi < 2; ++bi) {
        int K = KS[bi];
        int M = 8192 * K;
        float invn = 1.0f / (float)M;

        ball_kernel<<<2048, 128>>>(xyz, nxyz, idxb, R2[bi], K);
        gather_kernel<<<(M + 255) / 256, 256>>>(xyz, featT, nxyz, idxb, bufA, K);

        // L0: (O1 x 67) * X0 -> bufB
        {
            dim3 grid(OS[bi][1] / 64, M / 256);
            gemm_tc2_kernel<<<grid, 256, SMEM_GEMM>>>(
                OS[bi][1], OS[bi][0], IP[bi][0], M, K, wt + WOFF[bi][0],
                bufA, bufB, nullptr, nullptr, sum, sq, nullptr, nullptr);
            finalize_kernel<<<1, 256>>>(sum, sq, G[bi][0], Bb[bi][0], aa, ad, OS[bi][1], invn);
        }
        // L1: (O2 x O1) * act(bufB) -> bufA
        {
            dim3 grid(OS[bi][2] / 64, M / 256);
            gemm_tc2_kernel<<<grid, 256, SMEM_GEMM>>>(
                OS[bi][2], OS[bi][1], IP[bi][1], M, K, wt + WOFF[bi][1],
                bufB, bufA, aa, ad, sum, sq, nullptr, nullptr);
            finalize_kernel<<<1, 256>>>(sum, sq, G[bi][1], Bb[bi][1], aa, ad, OS[bi][2], invn);
        }
        // L2: (O3 x O2) * act(bufA) -> fused max/min epilogue (no Y write)
        {
            cudaMemsetAsync(emax, 0, (size_t)OS[bi][3] * 8192 * 4, 0);
            cudaMemsetAsync(emin, 0, (size_t)OS[bi][3] * 8192 * 4, 0);
            dim3 grid(OS[bi][3] / 64, M / 256);
            gemm_tc2_kernel<<<grid, 256, SMEM_GEMM>>>(
                OS[bi][3], OS[bi][2], IP[bi][2], M, K, wt + WOFF[bi][2],
                bufA, nullptr, aa, ad, sum, sq, emax, emin);
            finalize_kernel<<<1, 256>>>(sum, sq, G[bi][2], Bb[bi][2], aa, ad, OS[bi][3], invn);
        }
        // decode + final affine + relu -> output
        {
            int total = 8 * OS[bi][3] * 1024;
            maxfin_kernel<<<(total + 255) / 256, 256>>>(emax, emin, aa, ad, feat_out,
                                                        OS[bi][3], bi == 0 ? 0 : 128);
        }
    }
}